// round 10
// baseline (speedup 1.0000x reference)
#include <cuda_runtime.h>

// Problem constants (DgaRawSequence: B=256, T=8192, I=6, U=64, M=16)
#define NB 256
#define NT 8192
#define NI 6
#define NU 64
#define NM 16
#define UNFOLDS 6
#define EPSV 1e-8f

__device__ __forceinline__ float tanhf_(float v) {
    float y; asm("tanh.approx.f32 %0, %1;" : "=f"(y) : "f"(v)); return y;
}
__device__ __forceinline__ float rcpf_(float v) {
    float y; asm("rcp.approx.f32 %0, %1;" : "=f"(y) : "f"(v)); return y;
}

// sigmoid(z) = 0.5 + 0.5*tanh(z/2), 0.5's folded into weights.
//
// ONE 256-thread block = TWO independent 128-thread halves (batches b and
// b+128), each in the proven 64u x 2c layout. Warps 0-3 = half A, warps 4-7 =
// half B -> every SMSP hosts exactly one warp of each half.
//
// Burst tiling via a SINGLE rendezvous barrier (bar 3, count 256) per unfold,
// executed by both halves at DIFFERENT program points:
//   A: LDS -> tanh burst -> reduce -> SYNC3 -> STS -> bar1(128)
//   B: LDS -> SYNC3 -> tanh burst -> reduce -> STS -> bar2(128)
// On release, B bursts immediately while A runs its store/barrier tail, then
// A's next burst fills B's tail: the SMSP MUFU pipe stays ~continuously busy
// (period ~562 cyc vs 717 free-running). Every thread executes SYNC3 exactly
// once per unfold -> barrier counts always match -> deadlock-free, and the
// rendezvous re-locks the anti-phase every round (no drift).
__global__ void __launch_bounds__(256, 1) ltc_seq_kernel(
    const float* __restrict__ x,
    const float* __restrict__ gleak, const float* __restrict__ vleak,
    const float* __restrict__ cm,
    const float* __restrict__ sigma, const float* __restrict__ mu,
    const float* __restrict__ w,     const float* __restrict__ erev,
    const float* __restrict__ ssigma, const float* __restrict__ smu,
    const float* __restrict__ swv,    const float* __restrict__ serev,
    const float* __restrict__ in_w,  const float* __restrict__ in_b,
    const float* __restrict__ out_w, const float* __restrict__ out_b,
    float* __restrict__ out)
{
    const int tid  = threadIdx.x;
    const int half = tid >> 7;          // 0 = A (warps 0-3), 1 = B (warps 4-7)
    const int htid = tid & 127;
    const int u    = htid >> 1;
    const int c    = htid & 1;
    const int b    = blockIdx.x + half * 128;

    __shared__ __align__(16) float vbuf[2][2][NU];   // [half][pingpong][u]

    // ---- per-(j,u) recurrent params in registers, j = 32*c + k ----
    float p_na[32], p_tb[32], p_wh[32], p_weh[32];
    float denb = 0.f, numb = 0.f;
#pragma unroll
    for (int k = 0; k < 32; k++) {
        int j = c * 32 + k;
        float sg = sigma[j * NU + u];
        float m  = mu[j * NU + u];
        float ww = w[j * NU + u];
        float er = erev[j * NU + u];
        p_na[k]  = 0.5f * sg;
        p_tb[k]  = -0.5f * m * sg;
        p_wh[k]  = 0.5f * ww;
        p_weh[k] = 0.5f * ww * er;
        denb += p_wh[k];
        numb += p_weh[k];
    }

    // ---- sensory params: lane c handles i = 3c, 3c+1, 3c+2 ----
    float s_na[3], s_tb[3], s_wh[3], s_weh[3], s_iw[3], s_ib[3];
    float s_base_d = 0.f, s_base_n = 0.f;
#pragma unroll
    for (int ii = 0; ii < 3; ii++) {
        int i = c * 3 + ii;
        float sg = ssigma[i * NU + u], m = smu[i * NU + u];
        float ww = swv[i * NU + u],    er = serev[i * NU + u];
        s_na[ii]  = 0.5f * sg;
        s_tb[ii]  = -0.5f * m * sg;
        s_wh[ii]  = 0.5f * ww;
        s_weh[ii] = 0.5f * ww * er;
        s_base_d += s_wh[ii];
        s_base_n += s_weh[ii];
        s_iw[ii] = in_w[i]; s_ib[ii] = in_b[i];
    }

    // ---- per-u constants ----
    const float cmt  = 6.0f * cm[u];
    const float gl   = gleak[u];
    const float glvl = gl * vleak[u];
    float ow = 0.f, ob = 0.f;
    if (u < NM) { ow = out_w[u]; ob = out_b[u]; }

    // ---- init state v = 0 for both halves ----
    if (tid < 2 * NU) {
        ((float*)vbuf)[tid] = 0.f;          // halves' pingpong-0 and -1 (first 128 floats)
        ((float*)vbuf)[tid + 128] = 0.f;    // remaining 128 floats
    }
    __syncthreads();
    float vu = 0.f;   // register copy of v(u), redundant in both c-lanes

    const float* xb   = x   + (size_t)b * NT * NI;
    float*       outb = out + (size_t)b * NT * NM;

    float xv[3];
#pragma unroll
    for (int ii = 0; ii < 3; ii++) xv[ii] = xb[c * 3 + ii];

    for (int t = 0; t < NT; t++) {
        // ---- sensory sums for own batch (constant across unfolds) ----
        float ds = s_base_d, ns = s_base_n;
#pragma unroll
        for (int ii = 0; ii < 3; ii++) {
            float xi = fmaf(xv[ii], s_iw[ii], s_ib[ii]);
            float th = tanhf_(fmaf(xi, s_na[ii], s_tb[ii]));
            ds = fmaf(s_wh[ii],  th, ds);
            ns = fmaf(s_weh[ii], th, ns);
        }
        ds += __shfl_xor_sync(0xffffffffu, ds, 1);
        ns += __shfl_xor_sync(0xffffffffu, ns, 1);

        if (t + 1 < NT) {
#pragma unroll
            for (int ii = 0; ii < 3; ii++)
                xv[ii] = xb[(t + 1) * NI + c * 3 + ii];
        }

        const float nn_c = glvl + ns;
        const float dd_c = cmt + gl + ds + EPSV;

#pragma unroll
        for (int s = 0; s < UNFOLDS; s++) {
            const int rb = s & 1;
            const float* vp = vbuf[half][rb];

            // loop-top LDS (valid since own half's barrier of prev unfold)
            const float4* vp4 = (const float4*)(vp + c * 32);
            float vj[32];
#pragma unroll
            for (int q = 0; q < 8; q++) {
                float4 qq = vp4[q];
                vj[q * 4 + 0] = qq.x; vj[q * 4 + 1] = qq.y;
                vj[q * 4 + 2] = qq.z; vj[q * 4 + 3] = qq.w;
            }

            // B waits here: its burst starts only after A's burst+reduce.
            if (half == 1) {
                asm volatile("bar.sync 3, 256;" ::: "memory");
            }

            float den0 = denb, den1 = 0.f, num0 = numb, num1 = 0.f;
#pragma unroll
            for (int k = 0; k < 32; k++) {
                float th = tanhf_(fmaf(vj[k], p_na[k], p_tb[k]));
                if (k & 1) {
                    den1 = fmaf(p_wh[k],  th, den1);
                    num1 = fmaf(p_weh[k], th, num1);
                } else {
                    den0 = fmaf(p_wh[k],  th, den0);
                    num0 = fmaf(p_weh[k], th, num0);
                }
            }

            // den reduce FIRST so rcp (16cyc) overlaps num's shfl (26cyc)
            float den = den0 + den1;
            den += __shfl_xor_sync(0xffffffffu, den, 1);
            float num = num0 + num1;
            float r = rcpf_(dd_c + den);
            num += __shfl_xor_sync(0xffffffffu, num, 1);

            float nn = fmaf(cmt, vu, nn_c) + num;
            float vn = nn * r;
            vu = vn;

            // A rendezvous here: releases B's burst, then runs its tail
            // (STS + half-barrier) under B's burst.
            if (half == 0) {
                asm volatile("bar.sync 3, 256;" ::: "memory");
            }

            if (c == 0) vbuf[half][rb ^ 1][u] = vn;

            // per-half state barrier: only this half's 4 warps
            if (half == 0) {
                asm volatile("bar.sync 1, 128;" ::: "memory");
            } else {
                asm volatile("bar.sync 2, 128;" ::: "memory");
            }
        }

        // ---- output: first M motor neurons, affine ----
        if (c == 0 && u < NM) {
            outb[t * NM + u] = fmaf(vu, ow, ob);
        }
    }
}

extern "C" void kernel_launch(void* const* d_in, const int* in_sizes, int n_in,
                              void* d_out, int out_size) {
    (void)in_sizes; (void)n_in; (void)out_size;
    const float* xx     = (const float*)d_in[0];
    const float* gleak  = (const float*)d_in[1];
    const float* vleak  = (const float*)d_in[2];
    const float* cm     = (const float*)d_in[3];
    const float* sigma  = (const float*)d_in[4];
    const float* mu     = (const float*)d_in[5];
    const float* w      = (const float*)d_in[6];
    const float* erev   = (const float*)d_in[7];
    const float* ssig   = (const float*)d_in[8];
    const float* smu    = (const float*)d_in[9];
    const float* sw     = (const float*)d_in[10];
    const float* serev  = (const float*)d_in[11];
    const float* in_w   = (const float*)d_in[12];
    const float* in_b   = (const float*)d_in[13];
    const float* out_w  = (const float*)d_in[14];
    const float* out_b  = (const float*)d_in[15];
    float* out = (float*)d_out;

    ltc_seq_kernel<<<NB / 2, 256>>>(xx, gleak, vleak, cm, sigma, mu, w, erev,
                                    ssig, smu, sw, serev, in_w, in_b, out_w, out_b,
                                    out);
}

// round 11
// speedup vs baseline: 1.1429x; 1.1429x over previous
#include <cuda_runtime.h>

// Problem constants (DgaRawSequence: B=256, T=8192, I=6, U=64, M=16)
#define NB 256
#define NT 8192
#define NI 6
#define NU 64
#define NM 16
#define UNFOLDS 6
#define EPSV 1e-8f

__device__ __forceinline__ float tanhf_(float v) {
    float y; asm("tanh.approx.f32 %0, %1;" : "=f"(y) : "f"(v)); return y;
}
__device__ __forceinline__ float rcpf_(float v) {
    float y; asm("rcp.approx.f32 %0, %1;" : "=f"(y) : "f"(v)); return y;
}
__device__ __forceinline__ unsigned clk_() {
    unsigned c; asm volatile("mov.u32 %0, %%clock;" : "=r"(c)); return c;
}

// sigmoid(z) = 0.5 + 0.5*tanh(z/2), 0.5's folded into weights.
// Block = 128 threads = 64 u-neurons x 2 j-chunks (32 presynaptic j each).
// One block per batch (grid=256): 108 SMs host pairs (b, b+148), 40 host one.
//
// ANTI-PHASE: the per-unfold schedule is burst(256 cyc MUFU) + tail(~205 cyc
// shfl/rcp/STS/bar/LDS). Two phase-locked co-resident blocks give period
// 512+205=717. Simulation of the shared-MUFU dynamics shows that an initial
// offset > tail length falls into an ATTRACTING limit cycle of period ~480
// (each block bursts inside the other's tail). R6's FMA-chain delay was
// absorbed by param-load latency; here the offset is enforced in WALL TIME
// with a %clock spin (unabsorbable) on the second member of each pair.
__global__ void __launch_bounds__(128, 2) ltc_seq_kernel(
    const float* __restrict__ x,
    const float* __restrict__ gleak, const float* __restrict__ vleak,
    const float* __restrict__ cm,
    const float* __restrict__ sigma, const float* __restrict__ mu,
    const float* __restrict__ w,     const float* __restrict__ erev,
    const float* __restrict__ ssigma, const float* __restrict__ smu,
    const float* __restrict__ swv,    const float* __restrict__ serev,
    const float* __restrict__ in_w,  const float* __restrict__ in_b,
    const float* __restrict__ out_w, const float* __restrict__ out_b,
    float* __restrict__ out)
{
    const int tid = threadIdx.x;
    const int u   = tid >> 1;
    const int c   = tid & 1;
    const int b   = blockIdx.x;

    __shared__ __align__(16) float vbuf[2][NU];

    // ---- per-(j,u) recurrent params in registers, j = 32*c + k ----
    float p_na[32], p_tb[32], p_wh[32], p_weh[32];
    float denb = 0.f, numb = 0.f;   // sum of (w/2), (w*erev/2) bases
#pragma unroll
    for (int k = 0; k < 32; k++) {
        int j = c * 32 + k;
        float sg = sigma[j * NU + u];
        float m  = mu[j * NU + u];
        float ww = w[j * NU + u];
        float er = erev[j * NU + u];
        p_na[k]  = 0.5f * sg;            // multiplies v (z/2)
        p_tb[k]  = -0.5f * m * sg;       // constant term
        p_wh[k]  = 0.5f * ww;
        p_weh[k] = 0.5f * ww * er;
        denb += p_wh[k];
        numb += p_weh[k];
    }

    // ---- sensory params: lane c handles i = 3c, 3c+1, 3c+2 ----
    float s_na[3], s_tb[3], s_wh[3], s_weh[3], s_iw[3], s_ib[3];
    float s_base_d = 0.f, s_base_n = 0.f;
#pragma unroll
    for (int ii = 0; ii < 3; ii++) {
        int i = c * 3 + ii;
        float sg = ssigma[i * NU + u], m = smu[i * NU + u];
        float ww = swv[i * NU + u],    er = serev[i * NU + u];
        s_na[ii]  = 0.5f * sg;
        s_tb[ii]  = -0.5f * m * sg;
        s_wh[ii]  = 0.5f * ww;
        s_weh[ii] = 0.5f * ww * er;
        s_base_d += s_wh[ii];
        s_base_n += s_weh[ii];
        s_iw[ii] = in_w[i]; s_ib[ii] = in_b[i];
    }

    // ---- per-u constants ----
    const float cmt  = 6.0f * cm[u];     // cm / (elapsed/unfolds)
    const float gl   = gleak[u];
    const float glvl = gl * vleak[u];
    float ow = 0.f, ob = 0.f;
    if (u < NM) { ow = out_w[u]; ob = out_b[u]; }

    // ---- init state v = 0 ----
    if (tid < NU) vbuf[0][tid] = 0.f;
    __syncthreads();
    float vu = 0.f;   // register copy of v(u), redundant in both c-lanes

    // ---- anti-phase offset: wall-time spin for the second pair member ----
    // Co-resident pairs under the classic LUT are (b, b+148); give the b>=148
    // member a ~280-cycle REAL offset (clock-measured, cannot be absorbed by
    // load latency). Offset > tail(205) drops the pair into the ~480-cycle
    // anti-phase limit cycle instead of the 717-cycle phase-locked one.
    if (b >= 148) {
        unsigned s0 = clk_();
        while (clk_() - s0 < 280u) { }
    }

    const float* xb   = x   + (size_t)b * NT * NI;
    float*       outb = out + (size_t)b * NT * NM;

    // prefetch x for t=0
    float xv[3];
#pragma unroll
    for (int ii = 0; ii < 3; ii++) xv[ii] = xb[c * 3 + ii];

    for (int t = 0; t < NT; t++) {
        // ---- sensory sums (constant across unfolds) ----
        float ds = s_base_d, ns = s_base_n;
#pragma unroll
        for (int ii = 0; ii < 3; ii++) {
            float xi = fmaf(xv[ii], s_iw[ii], s_ib[ii]);
            float th = tanhf_(fmaf(xi, s_na[ii], s_tb[ii]));
            ds = fmaf(s_wh[ii],  th, ds);
            ns = fmaf(s_weh[ii], th, ns);
        }
        ds += __shfl_xor_sync(0xffffffffu, ds, 1);
        ns += __shfl_xor_sync(0xffffffffu, ns, 1);

        // ---- prefetch next timestep's x while unfolds run ----
        if (t + 1 < NT) {
#pragma unroll
            for (int ii = 0; ii < 3; ii++)
                xv[ii] = xb[(t + 1) * NI + c * 3 + ii];
        }

        // per-step constants folded once
        const float nn_c = glvl + ns;
        const float dd_c = cmt + gl + ds + EPSV;

#pragma unroll
        for (int s = 0; s < UNFOLDS; s++) {
            const int rb = s & 1;
            const float* vp = vbuf[rb];

            const float4* vp4 = (const float4*)(vp + c * 32);
            float vj[32];
#pragma unroll
            for (int q = 0; q < 8; q++) {
                float4 qq = vp4[q];
                vj[q * 4 + 0] = qq.x; vj[q * 4 + 1] = qq.y;
                vj[q * 4 + 2] = qq.z; vj[q * 4 + 3] = qq.w;
            }

            // two accumulator pairs for ILP; bases folded into pair 0
            float den0 = denb, den1 = 0.f, num0 = numb, num1 = 0.f;
#pragma unroll
            for (int k = 0; k < 32; k++) {
                float th = tanhf_(fmaf(vj[k], p_na[k], p_tb[k]));
                if (k & 1) {
                    den1 = fmaf(p_wh[k],  th, den1);
                    num1 = fmaf(p_weh[k], th, num1);
                } else {
                    den0 = fmaf(p_wh[k],  th, den0);
                    num0 = fmaf(p_weh[k], th, num0);
                }
            }
            // den reduce FIRST so rcp (16cyc) overlaps num's shfl (26cyc)
            float den = den0 + den1;
            den += __shfl_xor_sync(0xffffffffu, den, 1);
            float num = num0 + num1;
            float r = rcpf_(dd_c + den);
            num += __shfl_xor_sync(0xffffffffu, num, 1);

            float nn = fmaf(cmt, vu, nn_c) + num;
            float vn = nn * r;
            vu = vn;
            if (c == 0) vbuf[rb ^ 1][u] = vn;
            __syncthreads();
        }

        // ---- output: first M motor neurons, affine ----
        if (c == 0 && u < NM) {
            outb[t * NM + u] = fmaf(vu, ow, ob);
        }
    }
}

extern "C" void kernel_launch(void* const* d_in, const int* in_sizes, int n_in,
                              void* d_out, int out_size) {
    (void)in_sizes; (void)n_in; (void)out_size;
    const float* xx     = (const float*)d_in[0];
    const float* gleak  = (const float*)d_in[1];
    const float* vleak  = (const float*)d_in[2];
    const float* cm     = (const float*)d_in[3];
    const float* sigma  = (const float*)d_in[4];
    const float* mu     = (const float*)d_in[5];
    const float* w      = (const float*)d_in[6];
    const float* erev   = (const float*)d_in[7];
    const float* ssig   = (const float*)d_in[8];
    const float* smu    = (const float*)d_in[9];
    const float* sw     = (const float*)d_in[10];
    const float* serev  = (const float*)d_in[11];
    const float* in_w   = (const float*)d_in[12];
    const float* in_b   = (const float*)d_in[13];
    const float* out_w  = (const float*)d_in[14];
    const float* out_b  = (const float*)d_in[15];
    float* out = (float*)d_out;

    ltc_seq_kernel<<<NB, 128>>>(xx, gleak, vleak, cm, sigma, mu, w, erev,
                                ssig, smu, sw, serev, in_w, in_b, out_w, out_b,
                                out);
}